// round 1
// baseline (speedup 1.0000x reference)
#include <cuda_runtime.h>

// Problem constants
// B=8, N=1024, D=1024, H=16, dk=64
// inputs: query,key,value,adj,edges_att(unused),mask,Wq,bq,Wk,bk,Wv,bv,Wo,bo

__device__ float g_Q[8u * 1024u * 1024u];
__device__ float g_K[8u * 1024u * 1024u];
__device__ float g_V[8u * 1024u * 1024u];
__device__ float g_X[8u * 1024u * 1024u];
__device__ float g_inv[8u * 1024u];

// ---------------------------------------------------------------------------
// SGEMM with bias: C[M,Nc] = A[M,K] @ W[K,Nc] + bias[Nc]
// Block tile 128x128, K-tile 16, 256 threads, 8x8 per thread.
// M,Nc multiples of 128; K multiple of 16 (true here).
// ---------------------------------------------------------------------------
__global__ __launch_bounds__(256) void sgemm_bias(
    const float* __restrict__ A, const float* __restrict__ W,
    const float* __restrict__ bias, float* __restrict__ C,
    int M, int Nc, int K)
{
    __shared__ float As[16][128];  // transposed: As[k][m]
    __shared__ float Bs[16][128];  // Bs[k][n]

    const int tid = threadIdx.x;
    const int tr = tid >> 4;        // 0..15
    const int tc = tid & 15;        // 0..15
    const int rowBase = blockIdx.y * 128;
    const int colBase = blockIdx.x * 128;

    float acc[8][8];
#pragma unroll
    for (int i = 0; i < 8; i++)
#pragma unroll
        for (int j = 0; j < 8; j++) acc[i][j] = 0.f;

    const int aRow = tid >> 2;          // 0..63
    const int aCol = (tid & 3) << 2;    // 0,4,8,12
    const int bRow = tid >> 5;          // 0..7
    const int bCol = (tid & 31) << 2;   // 0..124

    for (int kt = 0; kt < K; kt += 16) {
#pragma unroll
        for (int p = 0; p < 2; p++) {
            int r = aRow + p * 64;
            float4 v = *(const float4*)(A + (size_t)(rowBase + r) * K + kt + aCol);
            As[aCol + 0][r] = v.x;
            As[aCol + 1][r] = v.y;
            As[aCol + 2][r] = v.z;
            As[aCol + 3][r] = v.w;
        }
#pragma unroll
        for (int p = 0; p < 2; p++) {
            int r = bRow + p * 8;
            *(float4*)(&Bs[r][bCol]) =
                *(const float4*)(W + (size_t)(kt + r) * Nc + colBase + bCol);
        }
        __syncthreads();

#pragma unroll
        for (int k = 0; k < 16; k++) {
            float4 a0 = *(const float4*)(&As[k][tr * 8]);
            float4 a1 = *(const float4*)(&As[k][tr * 8 + 4]);
            float4 b0 = *(const float4*)(&Bs[k][tc * 8]);
            float4 b1 = *(const float4*)(&Bs[k][tc * 8 + 4]);
            float ra[8] = {a0.x, a0.y, a0.z, a0.w, a1.x, a1.y, a1.z, a1.w};
            float rb[8] = {b0.x, b0.y, b0.z, b0.w, b1.x, b1.y, b1.z, b1.w};
#pragma unroll
            for (int i = 0; i < 8; i++)
#pragma unroll
                for (int j = 0; j < 8; j++) acc[i][j] += ra[i] * rb[j];
        }
        __syncthreads();
    }

#pragma unroll
    for (int i = 0; i < 8; i++) {
        int row = rowBase + tr * 8 + i;
#pragma unroll
        for (int j = 0; j < 8; j += 4) {
            int col = colBase + tc * 8 + j;
            float4 o;
            o.x = acc[i][j + 0] + bias[col + 0];
            o.y = acc[i][j + 1] + bias[col + 1];
            o.z = acc[i][j + 2] + bias[col + 2];
            o.w = acc[i][j + 3] + bias[col + 3];
            *(float4*)(C + (size_t)row * Nc + col) = o;
        }
    }
}

// ---------------------------------------------------------------------------
// adjacency row-sum -> 1/(sum+eps).  One block per row (B*N rows).
// ---------------------------------------------------------------------------
__global__ __launch_bounds__(256) void rowsum_inv(
    const float* __restrict__ adj, float* __restrict__ inv)
{
    __shared__ float red[256];
    const int row = blockIdx.x;
    const float* a = adj + (size_t)row * 1024;
    float s = 0.f;
    for (int i = threadIdx.x; i < 1024; i += 256) s += a[i];
    red[threadIdx.x] = s;
    __syncthreads();
    for (int o = 128; o > 0; o >>= 1) {
        if (threadIdx.x < o) red[threadIdx.x] += red[threadIdx.x + o];
        __syncthreads();
    }
    if (threadIdx.x == 0) inv[row] = 1.0f / (red[0] + 1e-6f);
}

// ---------------------------------------------------------------------------
// adj GEMM: X[b] += 0.5 * diag(inv[b]) * (adj[b] @ V[b])
// Per-batch 1024x1024x1024.  Same tiling as sgemm_bias.
// ---------------------------------------------------------------------------
__global__ __launch_bounds__(256) void adj_gemm(
    const float* __restrict__ ADJ, const float* __restrict__ Vfull,
    const float* __restrict__ inv, float* __restrict__ X)
{
    __shared__ float As[16][128];
    __shared__ float Bs[16][128];

    const int bidx = blockIdx.z;
    const float* A = ADJ + (size_t)bidx * 1024 * 1024;
    const float* W = Vfull + (size_t)bidx * 1024 * 1024;
    float* C = X + (size_t)bidx * 1024 * 1024;
    const float* ivr = inv + bidx * 1024;

    const int tid = threadIdx.x;
    const int tr = tid >> 4;
    const int tc = tid & 15;
    const int rowBase = blockIdx.y * 128;
    const int colBase = blockIdx.x * 128;

    float acc[8][8];
#pragma unroll
    for (int i = 0; i < 8; i++)
#pragma unroll
        for (int j = 0; j < 8; j++) acc[i][j] = 0.f;

    const int aRow = tid >> 2;
    const int aCol = (tid & 3) << 2;
    const int bRow = tid >> 5;
    const int bCol = (tid & 31) << 2;

    for (int kt = 0; kt < 1024; kt += 16) {
#pragma unroll
        for (int p = 0; p < 2; p++) {
            int r = aRow + p * 64;
            float4 v = *(const float4*)(A + (size_t)(rowBase + r) * 1024 + kt + aCol);
            As[aCol + 0][r] = v.x;
            As[aCol + 1][r] = v.y;
            As[aCol + 2][r] = v.z;
            As[aCol + 3][r] = v.w;
        }
#pragma unroll
        for (int p = 0; p < 2; p++) {
            int r = bRow + p * 8;
            *(float4*)(&Bs[r][bCol]) =
                *(const float4*)(W + (size_t)(kt + r) * 1024 + colBase + bCol);
        }
        __syncthreads();
#pragma unroll
        for (int k = 0; k < 16; k++) {
            float4 a0 = *(const float4*)(&As[k][tr * 8]);
            float4 a1 = *(const float4*)(&As[k][tr * 8 + 4]);
            float4 b0 = *(const float4*)(&Bs[k][tc * 8]);
            float4 b1 = *(const float4*)(&Bs[k][tc * 8 + 4]);
            float ra[8] = {a0.x, a0.y, a0.z, a0.w, a1.x, a1.y, a1.z, a1.w};
            float rb[8] = {b0.x, b0.y, b0.z, b0.w, b1.x, b1.y, b1.z, b1.w};
#pragma unroll
            for (int i = 0; i < 8; i++)
#pragma unroll
                for (int j = 0; j < 8; j++) acc[i][j] += ra[i] * rb[j];
        }
        __syncthreads();
    }

#pragma unroll
    for (int i = 0; i < 8; i++) {
        int row = rowBase + tr * 8 + i;
        float sc = 0.5f * ivr[row];
#pragma unroll
        for (int j = 0; j < 8; j += 4) {
            int col = colBase + tc * 8 + j;
            float4 old = *(const float4*)(C + (size_t)row * 1024 + col);
            float4 o;
            o.x = sc * acc[i][j + 0] + old.x;
            o.y = sc * acc[i][j + 1] + old.y;
            o.z = sc * acc[i][j + 2] + old.z;
            o.w = sc * acc[i][j + 3] + old.w;
            *(float4*)(C + (size_t)row * 1024 + col) = o;
        }
    }
}

// ---------------------------------------------------------------------------
// Flash-style attention half: X[b,q,h*64+c] = 0.5 * softmax(QK^T/8 masked) @ V
// Block: 32 queries x full key loop (64-key tiles), one (b,h) per blockIdx.{z,y}
// 128 threads: ty=tid/16 (4 query rows each), tx=tid%16 (4 cols each)
// Dynamic smem: Qs[32][68] | Ps[32][68] | KVs[64][68]  (K^T then V reuse)
// ---------------------------------------------------------------------------
#define PITCH 68

__global__ __launch_bounds__(128) void attn_kernel(
    const float* __restrict__ Q, const float* __restrict__ K,
    const float* __restrict__ V, const int* __restrict__ mask,
    float* __restrict__ X)
{
    extern __shared__ float sm[];
    float* Qs = sm;                // [32][PITCH]
    float* Ps = sm + 32 * PITCH;   // [32][PITCH]
    float* KVs = sm + 64 * PITCH;  // [64][PITCH]
    __shared__ int msk[64];

    const int tid = threadIdx.x;
    const int ty = tid >> 4;   // 0..7
    const int tx = tid & 15;   // 0..15
    const int b = blockIdx.z;
    const int h = blockIdx.y;
    const int q0 = blockIdx.x * 32;

    const float* Qb = Q + ((size_t)b * 1024 + q0) * 1024 + h * 64;
    const float* Kb = K + (size_t)b * 1024 * 1024 + h * 64;
    const float* Vb = V + (size_t)b * 1024 * 1024 + h * 64;
    const int* mb = mask + b * 1024;

    // load Q tile (32 x 64)
    for (int idx = tid; idx < 32 * 16; idx += 128) {
        int r = idx >> 4, c4 = (idx & 15) << 2;
        *(float4*)(&Qs[r * PITCH + c4]) =
            *(const float4*)(Qb + (size_t)r * 1024 + c4);
    }

    float m[4], l[4], O[4][4];
#pragma unroll
    for (int i = 0; i < 4; i++) {
        m[i] = -1e30f;
        l[i] = 0.f;
#pragma unroll
        for (int j = 0; j < 4; j++) O[i][j] = 0.f;
    }

    for (int kb = 0; kb < 1024; kb += 64) {
        __syncthreads();  // prior-iter reads of Ps/KVs done
        // K^T tile: KVs[d][c] = K[kb+c][d]
        for (int idx = tid; idx < 64 * 16; idx += 128) {
            int c = idx >> 4, d4 = (idx & 15) << 2;
            float4 v = *(const float4*)(Kb + (size_t)(kb + c) * 1024 + d4);
            KVs[(d4 + 0) * PITCH + c] = v.x;
            KVs[(d4 + 1) * PITCH + c] = v.y;
            KVs[(d4 + 2) * PITCH + c] = v.z;
            KVs[(d4 + 3) * PITCH + c] = v.w;
        }
        if (tid < 64) msk[tid] = mb[kb + tid];
        __syncthreads();

        // S = Q K^T
        float s[4][4];
#pragma unroll
        for (int i = 0; i < 4; i++)
#pragma unroll
            for (int j = 0; j < 4; j++) s[i][j] = 0.f;

#pragma unroll 4
        for (int d = 0; d < 64; d++) {
            float4 kv = *(const float4*)(&KVs[d * PITCH + tx * 4]);
#pragma unroll
            for (int i = 0; i < 4; i++) {
                float qv = Qs[(ty * 4 + i) * PITCH + d];
                s[i][0] += qv * kv.x;
                s[i][1] += qv * kv.y;
                s[i][2] += qv * kv.z;
                s[i][3] += qv * kv.w;
            }
        }

        // scale + key mask
#pragma unroll
        for (int j = 0; j < 4; j++) {
            bool dead = (msk[tx * 4 + j] == 0);
#pragma unroll
            for (int i = 0; i < 4; i++) {
                float v = s[i][j] * 0.125f;
                s[i][j] = dead ? -1e12f : v;
            }
        }

        // online softmax update per row
#pragma unroll
        for (int i = 0; i < 4; i++) {
            float tm = fmaxf(fmaxf(s[i][0], s[i][1]), fmaxf(s[i][2], s[i][3]));
#pragma unroll
            for (int o = 1; o < 16; o <<= 1)
                tm = fmaxf(tm, __shfl_xor_sync(0xffffffffu, tm, o));
            float mn = fmaxf(m[i], tm);
            float al = __expf(m[i] - mn);
            m[i] = mn;
            float ts = 0.f;
#pragma unroll
            for (int j = 0; j < 4; j++) {
                float p = __expf(s[i][j] - mn);
                s[i][j] = p;
                ts += p;
            }
#pragma unroll
            for (int o = 1; o < 16; o <<= 1)
                ts += __shfl_xor_sync(0xffffffffu, ts, o);
            l[i] = l[i] * al + ts;
#pragma unroll
            for (int j = 0; j < 4; j++) O[i][j] *= al;
        }

        // stage P
#pragma unroll
        for (int i = 0; i < 4; i++)
            *(float4*)(&Ps[(ty * 4 + i) * PITCH + tx * 4]) =
                make_float4(s[i][0], s[i][1], s[i][2], s[i][3]);
        __syncthreads();  // S-phase reads of KVs done, Ps staged

        // V tile: KVs[k][c]
        for (int idx = tid; idx < 64 * 16; idx += 128) {
            int r = idx >> 4, c4 = (idx & 15) << 2;
            *(float4*)(&KVs[r * PITCH + c4]) =
                *(const float4*)(Vb + (size_t)(kb + r) * 1024 + c4);
        }
        __syncthreads();

        // O += P @ V
#pragma unroll 4
        for (int k = 0; k < 64; k++) {
            float4 vv = *(const float4*)(&KVs[k * PITCH + tx * 4]);
#pragma unroll
            for (int i = 0; i < 4; i++) {
                float p = Ps[(ty * 4 + i) * PITCH + k];
                O[i][0] += p * vv.x;
                O[i][1] += p * vv.y;
                O[i][2] += p * vv.z;
                O[i][3] += p * vv.w;
            }
        }
    }

    // X = 0.5 * O / l
#pragma unroll
    for (int i = 0; i < 4; i++) {
        float sc = 0.5f / l[i];
        float4 o = make_float4(O[i][0] * sc, O[i][1] * sc, O[i][2] * sc, O[i][3] * sc);
        *(float4*)(X + ((size_t)b * 1024 + q0 + ty * 4 + i) * 1024 + h * 64 + tx * 4) = o;
    }
}

// ---------------------------------------------------------------------------
extern "C" void kernel_launch(void* const* d_in, const int* in_sizes, int n_in,
                              void* d_out, int out_size)
{
    const float* query = (const float*)d_in[0];
    const float* key   = (const float*)d_in[1];
    const float* value = (const float*)d_in[2];
    const float* adj   = (const float*)d_in[3];
    /* d_in[4] edges_att: unused by reference */
    const int*   mask  = (const int*)d_in[5];
    const float* Wq = (const float*)d_in[6];
    const float* bq = (const float*)d_in[7];
    const float* Wk = (const float*)d_in[8];
    const float* bk = (const float*)d_in[9];
    const float* Wv = (const float*)d_in[10];
    const float* bv = (const float*)d_in[11];
    const float* Wo = (const float*)d_in[12];
    const float* bo = (const float*)d_in[13];
    float* out = (float*)d_out;

    float *pQ, *pK, *pV, *pX, *pInv;
    cudaGetSymbolAddress((void**)&pQ, g_Q);
    cudaGetSymbolAddress((void**)&pK, g_K);
    cudaGetSymbolAddress((void**)&pV, g_V);
    cudaGetSymbolAddress((void**)&pX, g_X);
    cudaGetSymbolAddress((void**)&pInv, g_inv);

    dim3 gProj(1024 / 128, 8192 / 128);  // (8, 64)
    sgemm_bias<<<gProj, 256>>>(query, Wq, bq, pQ, 8192, 1024, 1024);
    sgemm_bias<<<gProj, 256>>>(key,   Wk, bk, pK, 8192, 1024, 1024);
    sgemm_bias<<<gProj, 256>>>(value, Wv, bv, pV, 8192, 1024, 1024);

    rowsum_inv<<<8192, 256>>>(adj, pInv);

    dim3 gAtt(1024 / 32, 16, 8);  // (32 q-tiles, H, B)
    size_t smemAtt = (size_t)(32 + 32 + 64) * PITCH * sizeof(float);  // 34816
    attn_kernel<<<gAtt, 128, smemAtt>>>(pQ, pK, pV, mask, pX);

    dim3 gAdj(1024 / 128, 1024 / 128, 8);
    adj_gemm<<<gAdj, 256>>>(adj, pV, pInv, pX);

    sgemm_bias<<<gProj, 256>>>(pX, Wo, bo, out, 8192, 1024, 1024);
}

// round 4
// speedup vs baseline: 1.7593x; 1.7593x over previous
#include <cuda_runtime.h>
#include <cstdint>

// ============================================================================
// Problem: B=8, N=1024, D=1024, H=16, dk=64
// out = (0.5*softmax(QK^T/8, key-masked) + 0.5*row_norm(adj)) @ V  -> @Wo + bo
// GEMMs run on tensor cores via mma.sync tf32 (sm_103 base target - no tcgen05).
// ============================================================================

__device__ float g_Q[8u * 1024u * 1024u];
__device__ float g_K[8u * 1024u * 1024u];
__device__ float g_V[8u * 1024u * 1024u];
__device__ float g_X[8u * 1024u * 1024u];
__device__ float g_inv[8u * 1024u];

// ---------------------------------------------------------------------------
// PTX helpers
// ---------------------------------------------------------------------------
__device__ __forceinline__ uint32_t smem_to_u32(const void* p) {
    uint32_t a;
    asm("{ .reg .u64 t; cvta.to.shared.u64 t, %1; cvt.u32.u64 %0, t; }" : "=r"(a) : "l"(p));
    return a;
}
__device__ __forceinline__ void cp_async16(uint32_t s, const void* g) {
    asm volatile("cp.async.cg.shared.global [%0], [%1], 16;" :: "r"(s), "l"(g));
}
#define CP_COMMIT() asm volatile("cp.async.commit_group;" ::: "memory")
#define CP_WAIT(n)  asm volatile("cp.async.wait_group %0;" :: "n"(n) : "memory")

__device__ __forceinline__ uint32_t f2tf32(float x) {
    uint32_t r;
    asm("cvt.rna.tf32.f32 %0, %1;" : "=r"(r) : "f"(x));
    return r;
}
__device__ __forceinline__ void mma_tf32(float* c, const uint32_t* a, const uint32_t* b) {
    asm volatile(
        "mma.sync.aligned.m16n8k8.row.col.f32.tf32.tf32.f32 "
        "{%0,%1,%2,%3}, {%4,%5,%6,%7}, {%8,%9}, {%0,%1,%2,%3};"
        : "+f"(c[0]), "+f"(c[1]), "+f"(c[2]), "+f"(c[3])
        : "r"(a[0]), "r"(a[1]), "r"(a[2]), "r"(a[3]), "r"(b[0]), "r"(b[1]));
}

// ---------------------------------------------------------------------------
// tf32 tensor-core GEMM.
// C[M, 1024] = A[M,1024] @ B[1024,1024]  (both row-major fp32)
// Block tile 128x256, 8 warps (2x4), warp tile 64x64, K-tile 32, 2-stage cp.async.
// mode 0: C = D + bias[col]
// mode 1: C = 0.5*inv[z*1024+row]*D + Xin[row,col]
// ---------------------------------------------------------------------------
#define PA 36    // A smem pitch (floats): fragment bank = 4g+t -> conflict-free
#define PB 264   // B smem pitch (floats): fragment bank = 8t+g -> conflict-free
#define A_STG (128 * PA)          // 4608 floats
#define B_STG (32 * PB)           // 8448 floats
#define GEMM_SMEM ((A_STG + B_STG) * 2 * 4)  // 104448 bytes

__global__ __launch_bounds__(256, 1) void gemm_tf32(
    const float* __restrict__ A, const float* __restrict__ B,
    const float* __restrict__ bias, const float* __restrict__ inv,
    const float* __restrict__ Xin, float* __restrict__ C,
    size_t sA, size_t sB, size_t sC, int mode)
{
    extern __shared__ float sm[];
    float* As[2] = { sm, sm + A_STG };
    float* Bs[2] = { sm + 2 * A_STG, sm + 2 * A_STG + B_STG };
    const uint32_t As_u[2] = { smem_to_u32(As[0]), smem_to_u32(As[1]) };
    const uint32_t Bs_u[2] = { smem_to_u32(Bs[0]), smem_to_u32(Bs[1]) };

    const int tid = threadIdx.x;
    const int wid = tid >> 5, lane = tid & 31;
    const int wm = wid >> 2, wn = wid & 3;       // warp grid 2 x 4
    const int g = lane >> 2, t = lane & 3;

    const int z = blockIdx.z;
    const float* Ab = A + (size_t)z * sA + (size_t)(blockIdx.y * 128) * 1024;
    const float* Bb = B + (size_t)z * sB + blockIdx.x * 256;

    // load indices (per thread)
    const int a_row = tid >> 3, a_c4 = (tid & 7) << 2;        // +i*32 rows
    const int b_row = tid >> 6, b_c4 = (tid & 63) << 2;       // +i*4 rows

    float c[4][8][4];
#pragma unroll
    for (int i = 0; i < 4; i++)
#pragma unroll
        for (int j = 0; j < 8; j++)
#pragma unroll
            for (int q = 0; q < 4; q++) c[i][j][q] = 0.f;

    // ---- async tile loader ----
    auto load_stage = [&](int kt, int stg) {
#pragma unroll
        for (int i = 0; i < 4; i++) {
            int r = a_row + i * 32;
            cp_async16(As_u[stg] + (uint32_t)(r * PA + a_c4) * 4,
                       Ab + (size_t)r * 1024 + kt * 32 + a_c4);
        }
#pragma unroll
        for (int i = 0; i < 8; i++) {
            int r = b_row + i * 4;
            cp_async16(Bs_u[stg] + (uint32_t)(r * PB + b_c4) * 4,
                       Bb + (size_t)(kt * 32 + r) * 1024 + b_c4);
        }
        CP_COMMIT();
    };

    load_stage(0, 0);

    for (int kt = 0; kt < 32; kt++) {
        const int stg = kt & 1;
        if (kt + 1 < 32) {
            load_stage(kt + 1, stg ^ 1);
            CP_WAIT(1);
        } else {
            CP_WAIT(0);
        }
        __syncthreads();

        const float* Ast = As[stg];
        const float* Bst = Bs[stg];
#pragma unroll
        for (int ks = 0; ks < 4; ks++) {
            const int k0 = ks * 8;
            uint32_t af[4][4];
#pragma unroll
            for (int i = 0; i < 4; i++) {
                const float* ar = Ast + (wm * 64 + i * 16 + g) * PA + k0 + t;
                af[i][0] = f2tf32(ar[0]);
                af[i][1] = f2tf32(ar[8 * PA]);
                af[i][2] = f2tf32(ar[4]);
                af[i][3] = f2tf32(ar[8 * PA + 4]);
            }
            uint32_t bf[8][2];
#pragma unroll
            for (int j = 0; j < 8; j++) {
                const float* br = Bst + (k0 + t) * PB + wn * 64 + j * 8 + g;
                bf[j][0] = f2tf32(br[0]);
                bf[j][1] = f2tf32(br[4 * PB]);
            }
#pragma unroll
            for (int i = 0; i < 4; i++)
#pragma unroll
                for (int j = 0; j < 8; j++)
                    mma_tf32(c[i][j], af[i], bf[j]);
        }
        __syncthreads();
    }

    // ---- epilogue ----
    const int colW = blockIdx.x * 256 + wn * 64;
    float* Cz = C + (size_t)z * sC;
    const float* Xz = Xin + (size_t)z * sC;

#pragma unroll
    for (int i = 0; i < 4; i++) {
        const int row0 = blockIdx.y * 128 + wm * 64 + i * 16 + g;
        const int row1 = row0 + 8;
        if (mode == 0) {
#pragma unroll
            for (int j = 0; j < 8; j++) {
                const int col = colW + j * 8 + 2 * t;
                const float b0 = bias[col], b1 = bias[col + 1];
                *(float2*)(Cz + (size_t)row0 * 1024 + col) =
                    make_float2(c[i][j][0] + b0, c[i][j][1] + b1);
                *(float2*)(Cz + (size_t)row1 * 1024 + col) =
                    make_float2(c[i][j][2] + b0, c[i][j][3] + b1);
            }
        } else {
            const float s0 = 0.5f * inv[z * 1024 + row0];
            const float s1 = 0.5f * inv[z * 1024 + row1];
#pragma unroll
            for (int j = 0; j < 8; j++) {
                const int col = colW + j * 8 + 2 * t;
                float2 x0 = *(const float2*)(Xz + (size_t)row0 * 1024 + col);
                float2 x1 = *(const float2*)(Xz + (size_t)row1 * 1024 + col);
                *(float2*)(Cz + (size_t)row0 * 1024 + col) =
                    make_float2(s0 * c[i][j][0] + x0.x, s0 * c[i][j][1] + x0.y);
                *(float2*)(Cz + (size_t)row1 * 1024 + col) =
                    make_float2(s1 * c[i][j][2] + x1.x, s1 * c[i][j][3] + x1.y);
            }
        }
    }
}

// ---------------------------------------------------------------------------
// adjacency row-sum -> 1/(sum+eps)
// ---------------------------------------------------------------------------
__global__ __launch_bounds__(256) void rowsum_inv(
    const float* __restrict__ adj, float* __restrict__ inv)
{
    __shared__ float red[256];
    const int row = blockIdx.x;
    const float* a = adj + (size_t)row * 1024;
    float s = 0.f;
    for (int i = threadIdx.x; i < 1024; i += 256) s += a[i];
    red[threadIdx.x] = s;
    __syncthreads();
    for (int o = 128; o > 0; o >>= 1) {
        if (threadIdx.x < o) red[threadIdx.x] += red[threadIdx.x + o];
        __syncthreads();
    }
    if (threadIdx.x == 0) inv[row] = 1.0f / (red[0] + 1e-6f);
}

// ---------------------------------------------------------------------------
// Flash-style attention half (fp32):
// X[b,q,h*64+c] = 0.5 * softmax(QK^T/8 masked) @ V
// ---------------------------------------------------------------------------
#define PITCH 68

__global__ __launch_bounds__(128) void attn_kernel(
    const float* __restrict__ Q, const float* __restrict__ K,
    const float* __restrict__ V, const int* __restrict__ mask,
    float* __restrict__ X)
{
    extern __shared__ float smf[];
    float* Qs = smf;
    float* Ps = smf + 32 * PITCH;
    float* KVs = smf + 64 * PITCH;
    __shared__ int msk[64];

    const int tid = threadIdx.x;
    const int ty = tid >> 4;
    const int tx = tid & 15;
    const int b = blockIdx.z;
    const int h = blockIdx.y;
    const int q0 = blockIdx.x * 32;

    const float* Qb = Q + ((size_t)b * 1024 + q0) * 1024 + h * 64;
    const float* Kb = K + (size_t)b * 1024 * 1024 + h * 64;
    const float* Vb = V + (size_t)b * 1024 * 1024 + h * 64;
    const int* mb = mask + b * 1024;

    for (int idx = tid; idx < 32 * 16; idx += 128) {
        int r = idx >> 4, c4 = (idx & 15) << 2;
        *(float4*)(&Qs[r * PITCH + c4]) = *(const float4*)(Qb + (size_t)r * 1024 + c4);
    }

    float m[4], l[4], O[4][4];
#pragma unroll
    for (int i = 0; i < 4; i++) {
        m[i] = -1e30f; l[i] = 0.f;
#pragma unroll
        for (int j = 0; j < 4; j++) O[i][j] = 0.f;
    }

    for (int kb = 0; kb < 1024; kb += 64) {
        __syncthreads();
        for (int idx = tid; idx < 64 * 16; idx += 128) {
            int cc = idx >> 4, d4 = (idx & 15) << 2;
            float4 v = *(const float4*)(Kb + (size_t)(kb + cc) * 1024 + d4);
            KVs[(d4 + 0) * PITCH + cc] = v.x;
            KVs[(d4 + 1) * PITCH + cc] = v.y;
            KVs[(d4 + 2) * PITCH + cc] = v.z;
            KVs[(d4 + 3) * PITCH + cc] = v.w;
        }
        if (tid < 64) msk[tid] = mb[kb + tid];
        __syncthreads();

        float s[4][4];
#pragma unroll
        for (int i = 0; i < 4; i++)
#pragma unroll
            for (int j = 0; j < 4; j++) s[i][j] = 0.f;

#pragma unroll 4
        for (int d = 0; d < 64; d++) {
            float4 kv = *(const float4*)(&KVs[d * PITCH + tx * 4]);
#pragma unroll
            for (int i = 0; i < 4; i++) {
                float qv = Qs[(ty * 4 + i) * PITCH + d];
                s[i][0] += qv * kv.x;
                s[i][1] += qv * kv.y;
                s[i][2] += qv * kv.z;
                s[i][3] += qv * kv.w;
            }
        }

#pragma unroll
        for (int j = 0; j < 4; j++) {
            bool dead = (msk[tx * 4 + j] == 0);
#pragma unroll
            for (int i = 0; i < 4; i++) {
                float v = s[i][j] * 0.125f;
                s[i][j] = dead ? -1e12f : v;
            }
        }

#pragma unroll
        for (int i = 0; i < 4; i++) {
            float tm = fmaxf(fmaxf(s[i][0], s[i][1]), fmaxf(s[i][2], s[i][3]));
#pragma unroll
            for (int o = 1; o < 16; o <<= 1)
                tm = fmaxf(tm, __shfl_xor_sync(0xffffffffu, tm, o));
            float mn = fmaxf(m[i], tm);
            float al = __expf(m[i] - mn);
            m[i] = mn;
            float ts = 0.f;
#pragma unroll
            for (int j = 0; j < 4; j++) {
                float p = __expf(s[i][j] - mn);
                s[i][j] = p;
                ts += p;
            }
#pragma unroll
            for (int o = 1; o < 16; o <<= 1)
                ts += __shfl_xor_sync(0xffffffffu, ts, o);
            l[i] = l[i] * al + ts;
#pragma unroll
            for (int j = 0; j < 4; j++) O[i][j] *= al;
        }

#pragma unroll
        for (int i = 0; i < 4; i++)
            *(float4*)(&Ps[(ty * 4 + i) * PITCH + tx * 4]) =
                make_float4(s[i][0], s[i][1], s[i][2], s[i][3]);
        __syncthreads();

        for (int idx = tid; idx < 64 * 16; idx += 128) {
            int r = idx >> 4, c4 = (idx & 15) << 2;
            *(float4*)(&KVs[r * PITCH + c4]) =
                *(const float4*)(Vb + (size_t)(kb + r) * 1024 + c4);
        }
        __syncthreads();

#pragma unroll 4
        for (int k = 0; k < 64; k++) {
            float4 vv = *(const float4*)(&KVs[k * PITCH + tx * 4]);
#pragma unroll
            for (int i = 0; i < 4; i++) {
                float p = Ps[(ty * 4 + i) * PITCH + k];
                O[i][0] += p * vv.x;
                O[i][1] += p * vv.y;
                O[i][2] += p * vv.z;
                O[i][3] += p * vv.w;
            }
        }
    }

#pragma unroll
    for (int i = 0; i < 4; i++) {
        float sc = 0.5f / l[i];
        float4 o = make_float4(O[i][0] * sc, O[i][1] * sc, O[i][2] * sc, O[i][3] * sc);
        *(float4*)(X + ((size_t)b * 1024 + q0 + ty * 4 + i) * 1024 + h * 64 + tx * 4) = o;
    }
}

// ---------------------------------------------------------------------------
extern "C" void kernel_launch(void* const* d_in, const int* in_sizes, int n_in,
                              void* d_out, int out_size)
{
    const float* query = (const float*)d_in[0];
    const float* key   = (const float*)d_in[1];
    const float* value = (const float*)d_in[2];
    const float* adj   = (const float*)d_in[3];
    const int*   mask  = (const int*)d_in[5];
    const float* Wq = (const float*)d_in[6];
    const float* bq = (const float*)d_in[7];
    const float* Wk = (const float*)d_in[8];
    const float* bk = (const float*)d_in[9];
    const float* Wv = (const float*)d_in[10];
    const float* bv = (const float*)d_in[11];
    const float* Wo = (const float*)d_in[12];
    const float* bo = (const float*)d_in[13];
    float* out = (float*)d_out;

    float *pQ, *pK, *pV, *pX, *pInv;
    cudaGetSymbolAddress((void**)&pQ, g_Q);
    cudaGetSymbolAddress((void**)&pK, g_K);
    cudaGetSymbolAddress((void**)&pV, g_V);
    cudaGetSymbolAddress((void**)&pX, g_X);
    cudaGetSymbolAddress((void**)&pInv, g_inv);

    cudaFuncSetAttribute(gemm_tf32, cudaFuncAttributeMaxDynamicSharedMemorySize, GEMM_SMEM);

    dim3 gProj(4, 64, 1);   // 1024/256 cols x 8192/128 rows

    // projections (tensor core tf32)
    gemm_tf32<<<gProj, 256, GEMM_SMEM>>>(query, Wq, bq, nullptr, nullptr, pQ, 0, 0, 0, 0);
    gemm_tf32<<<gProj, 256, GEMM_SMEM>>>(key,   Wk, bk, nullptr, nullptr, pK, 0, 0, 0, 0);
    gemm_tf32<<<gProj, 256, GEMM_SMEM>>>(value, Wv, bv, nullptr, nullptr, pV, 0, 0, 0, 0);

    rowsum_inv<<<8192, 256>>>(adj, pInv);

    // attention half -> X
    dim3 gAtt(1024 / 32, 16, 8);
    size_t smemAtt = (size_t)(32 + 32 + 64) * PITCH * sizeof(float);
    attn_kernel<<<gAtt, 128, smemAtt>>>(pQ, pK, pV, mask, pX);

    // adjacency half: X += 0.5 * diag(inv) * (adj @ V), batched
    gemm_tf32<<<dim3(4, 8, 8), 256, GEMM_SMEM>>>(
        adj, pV, nullptr, pInv, pX, pX,
        (size_t)1024 * 1024, (size_t)1024 * 1024, (size_t)1024 * 1024, 1);

    // output projection
    gemm_tf32<<<gProj, 256, GEMM_SMEM>>>(pX, Wo, bo, nullptr, nullptr, out, 0, 0, 0, 0);
}

// round 5
// speedup vs baseline: 2.8093x; 1.5968x over previous
#include <cuda_runtime.h>
#include <cstdint>

// ============================================================================
// Problem: B=8, N=1024, D=1024, H=16, dk=64
// out = (0.5*softmax(QK^T/8, key-masked) + 0.5*row_norm(adj)) @ V  -> @Wo + bo
// All GEMMs + attention products on tensor cores via mma.sync tf32.
// ============================================================================

__device__ float g_Q[8u * 1024u * 1024u];
__device__ float g_K[8u * 1024u * 1024u];
__device__ float g_V[8u * 1024u * 1024u];
__device__ float g_X[8u * 1024u * 1024u];
__device__ float g_inv[8u * 1024u];

// ---------------------------------------------------------------------------
// PTX helpers
// ---------------------------------------------------------------------------
__device__ __forceinline__ uint32_t smem_to_u32(const void* p) {
    uint32_t a;
    asm("{ .reg .u64 t; cvta.to.shared.u64 t, %1; cvt.u32.u64 %0, t; }" : "=r"(a) : "l"(p));
    return a;
}
__device__ __forceinline__ void cp_async16(uint32_t s, const void* g) {
    asm volatile("cp.async.cg.shared.global [%0], [%1], 16;" :: "r"(s), "l"(g));
}
#define CP_COMMIT() asm volatile("cp.async.commit_group;" ::: "memory")
#define CP_WAIT(n)  asm volatile("cp.async.wait_group %0;" :: "n"(n) : "memory")

__device__ __forceinline__ uint32_t f2tf32(float x) {
    uint32_t r;
    asm("cvt.rna.tf32.f32 %0, %1;" : "=r"(r) : "f"(x));
    return r;
}
__device__ __forceinline__ void mma_tf32(float* c, const uint32_t* a, const uint32_t* b) {
    asm volatile(
        "mma.sync.aligned.m16n8k8.row.col.f32.tf32.tf32.f32 "
        "{%0,%1,%2,%3}, {%4,%5,%6,%7}, {%8,%9}, {%0,%1,%2,%3};"
        : "+f"(c[0]), "+f"(c[1]), "+f"(c[2]), "+f"(c[3])
        : "r"(a[0]), "r"(a[1]), "r"(a[2]), "r"(a[3]), "r"(b[0]), "r"(b[1]));
}

// ---------------------------------------------------------------------------
// tf32 tensor-core GEMM (unchanged from R4, validated).
// C[M, 1024] = A[M,1024] @ B[1024,1024]  (both row-major fp32)
// mode 0: C = D + bias[col];  mode 1: C = 0.5*inv[z*1024+row]*D + Xin
// ---------------------------------------------------------------------------
#define PA 36
#define PB 264
#define A_STG (128 * PA)
#define B_STG (32 * PB)
#define GEMM_SMEM ((A_STG + B_STG) * 2 * 4)

__global__ __launch_bounds__(256, 1) void gemm_tf32(
    const float* __restrict__ A, const float* __restrict__ B,
    const float* __restrict__ bias, const float* __restrict__ inv,
    const float* __restrict__ Xin, float* __restrict__ C,
    size_t sA, size_t sB, size_t sC, int mode)
{
    extern __shared__ float sm[];
    float* As[2] = { sm, sm + A_STG };
    float* Bs[2] = { sm + 2 * A_STG, sm + 2 * A_STG + B_STG };
    const uint32_t As_u[2] = { smem_to_u32(As[0]), smem_to_u32(As[1]) };
    const uint32_t Bs_u[2] = { smem_to_u32(Bs[0]), smem_to_u32(Bs[1]) };

    const int tid = threadIdx.x;
    const int wid = tid >> 5, lane = tid & 31;
    const int wm = wid >> 2, wn = wid & 3;
    const int g = lane >> 2, t = lane & 3;

    const int z = blockIdx.z;
    const float* Ab = A + (size_t)z * sA + (size_t)(blockIdx.y * 128) * 1024;
    const float* Bb = B + (size_t)z * sB + blockIdx.x * 256;

    const int a_row = tid >> 3, a_c4 = (tid & 7) << 2;
    const int b_row = tid >> 6, b_c4 = (tid & 63) << 2;

    float c[4][8][4];
#pragma unroll
    for (int i = 0; i < 4; i++)
#pragma unroll
        for (int j = 0; j < 8; j++)
#pragma unroll
            for (int q = 0; q < 4; q++) c[i][j][q] = 0.f;

    auto load_stage = [&](int kt, int stg) {
#pragma unroll
        for (int i = 0; i < 4; i++) {
            int r = a_row + i * 32;
            cp_async16(As_u[stg] + (uint32_t)(r * PA + a_c4) * 4,
                       Ab + (size_t)r * 1024 + kt * 32 + a_c4);
        }
#pragma unroll
        for (int i = 0; i < 8; i++) {
            int r = b_row + i * 4;
            cp_async16(Bs_u[stg] + (uint32_t)(r * PB + b_c4) * 4,
                       Bb + (size_t)(kt * 32 + r) * 1024 + b_c4);
        }
        CP_COMMIT();
    };

    load_stage(0, 0);

    for (int kt = 0; kt < 32; kt++) {
        const int stg = kt & 1;
        if (kt + 1 < 32) { load_stage(kt + 1, stg ^ 1); CP_WAIT(1); }
        else             { CP_WAIT(0); }
        __syncthreads();

        const float* Ast = As[stg];
        const float* Bst = Bs[stg];
#pragma unroll
        for (int ks = 0; ks < 4; ks++) {
            const int k0 = ks * 8;
            uint32_t af[4][4];
#pragma unroll
            for (int i = 0; i < 4; i++) {
                const float* ar = Ast + (wm * 64 + i * 16 + g) * PA + k0 + t;
                af[i][0] = f2tf32(ar[0]);
                af[i][1] = f2tf32(ar[8 * PA]);
                af[i][2] = f2tf32(ar[4]);
                af[i][3] = f2tf32(ar[8 * PA + 4]);
            }
            uint32_t bf[8][2];
#pragma unroll
            for (int j = 0; j < 8; j++) {
                const float* br = Bst + (k0 + t) * PB + wn * 64 + j * 8 + g;
                bf[j][0] = f2tf32(br[0]);
                bf[j][1] = f2tf32(br[4 * PB]);
            }
#pragma unroll
            for (int i = 0; i < 4; i++)
#pragma unroll
                for (int j = 0; j < 8; j++)
                    mma_tf32(c[i][j], af[i], bf[j]);
        }
        __syncthreads();
    }

    const int colW = blockIdx.x * 256 + wn * 64;
    float* Cz = C + (size_t)z * sC;
    const float* Xz = Xin + (size_t)z * sC;

#pragma unroll
    for (int i = 0; i < 4; i++) {
        const int row0 = blockIdx.y * 128 + wm * 64 + i * 16 + g;
        const int row1 = row0 + 8;
        if (mode == 0) {
#pragma unroll
            for (int j = 0; j < 8; j++) {
                const int col = colW + j * 8 + 2 * t;
                const float b0 = bias[col], b1 = bias[col + 1];
                *(float2*)(Cz + (size_t)row0 * 1024 + col) =
                    make_float2(c[i][j][0] + b0, c[i][j][1] + b1);
                *(float2*)(Cz + (size_t)row1 * 1024 + col) =
                    make_float2(c[i][j][2] + b0, c[i][j][3] + b1);
            }
        } else {
            const float s0 = 0.5f * inv[z * 1024 + row0];
            const float s1 = 0.5f * inv[z * 1024 + row1];
#pragma unroll
            for (int j = 0; j < 8; j++) {
                const int col = colW + j * 8 + 2 * t;
                float2 x0 = *(const float2*)(Xz + (size_t)row0 * 1024 + col);
                float2 x1 = *(const float2*)(Xz + (size_t)row1 * 1024 + col);
                *(float2*)(Cz + (size_t)row0 * 1024 + col) =
                    make_float2(s0 * c[i][j][0] + x0.x, s0 * c[i][j][1] + x0.y);
                *(float2*)(Cz + (size_t)row1 * 1024 + col) =
                    make_float2(s1 * c[i][j][2] + x1.x, s1 * c[i][j][3] + x1.y);
            }
        }
    }
}

// ---------------------------------------------------------------------------
// adjacency row-sum -> 1/(sum+eps)
// ---------------------------------------------------------------------------
__global__ __launch_bounds__(256) void rowsum_inv(
    const float* __restrict__ adj, float* __restrict__ inv)
{
    __shared__ float red[256];
    const int row = blockIdx.x;
    const float* a = adj + (size_t)row * 1024;
    float s = 0.f;
    for (int i = threadIdx.x; i < 1024; i += 256) s += a[i];
    red[threadIdx.x] = s;
    __syncthreads();
    for (int o = 128; o > 0; o >>= 1) {
        if (threadIdx.x < o) red[threadIdx.x] += red[threadIdx.x + o];
        __syncthreads();
    }
    if (threadIdx.x == 0) inv[row] = 1.0f / (red[0] + 1e-6f);
}

// ---------------------------------------------------------------------------
// Tensor-core flash attention half:
// X[b, q, h*64+d] = 0.5 * softmax(QK^T/8, key-masked) @ V
// Block = 64 queries of one (b,h); 4 warps, each owns 16 q-rows (m16).
// S = Q K^T via m16n8k8 tf32 (B-frag reads K[key][d] directly, no transpose).
// P staged per-warp in smem as tf32 bits; O += P V (B-frag reads V[key][d]).
// Smem tiles pre-converted to tf32 bit patterns at load time.
// ---------------------------------------------------------------------------
#define QP 68   // Q/K/P pitch (uint32): frag reads hit banks 4g+t -> clean
#define VP 72   // V pitch: frag reads hit banks 8t+g -> clean
#define ATT_SMEM ((64 * (3 * QP + VP)) * 4)   // 70656 bytes

__global__ __launch_bounds__(128) void attn_tc(
    const float* __restrict__ Q, const float* __restrict__ K,
    const float* __restrict__ V, const int* __restrict__ mask,
    float* __restrict__ X)
{
    extern __shared__ uint32_t smu[];
    uint32_t* Qs = smu;                 // [64][QP]
    uint32_t* Ks = smu + 64 * QP;       // [64][QP]
    uint32_t* Ps = smu + 128 * QP;      // [64][QP]
    uint32_t* Vs = smu + 192 * QP;      // [64][VP]
    __shared__ int msk[64];

    const int tid = threadIdx.x;
    const int wid = tid >> 5, lane = tid & 31;
    const int g = lane >> 2, t = lane & 3;
    const int b = blockIdx.z, h = blockIdx.y;
    const int q0 = blockIdx.x * 64;

    const float* Qb = Q + ((size_t)b * 1024 + q0) * 1024 + h * 64;
    const float* Kb = K + (size_t)b * 1024 * 1024 + h * 64;
    const float* Vb = V + (size_t)b * 1024 * 1024 + h * 64;
    const int* mb = mask + b * 1024;

    // load Q tile 64x64 as tf32 bits
    for (int idx = tid; idx < 64 * 16; idx += 128) {
        int r = idx >> 4, c4 = (idx & 15) << 2;
        float4 v = *(const float4*)(Qb + (size_t)r * 1024 + c4);
        uint32_t* d = Qs + r * QP + c4;
        d[0] = f2tf32(v.x); d[1] = f2tf32(v.y);
        d[2] = f2tf32(v.z); d[3] = f2tf32(v.w);
    }

    float m0 = -1e30f, m1 = -1e30f, l0 = 0.f, l1 = 0.f;
    float o[8][4];
#pragma unroll
    for (int j = 0; j < 8; j++)
#pragma unroll
        for (int q = 0; q < 4; q++) o[j][q] = 0.f;

    const int rowA = wid * 16 + g;     // a-frag base row (and +8)

    for (int kb = 0; kb < 1024; kb += 64) {
        __syncthreads();   // previous iter's reads of Ks/Vs complete
        // K and V tiles (64 keys x 64 d), tf32 bits
        for (int idx = tid; idx < 64 * 16; idx += 128) {
            int r = idx >> 4, c4 = (idx & 15) << 2;
            float4 kv = *(const float4*)(Kb + (size_t)(kb + r) * 1024 + c4);
            uint32_t* dk = Ks + r * QP + c4;
            dk[0] = f2tf32(kv.x); dk[1] = f2tf32(kv.y);
            dk[2] = f2tf32(kv.z); dk[3] = f2tf32(kv.w);
            float4 vv = *(const float4*)(Vb + (size_t)(kb + r) * 1024 + c4);
            uint32_t* dv = Vs + r * VP + c4;
            dv[0] = f2tf32(vv.x); dv[1] = f2tf32(vv.y);
            dv[2] = f2tf32(vv.z); dv[3] = f2tf32(vv.w);
        }
        if (tid < 64) msk[tid] = mb[kb + tid];
        __syncthreads();

        // ---- S = Q K^T (rows rowA/rowA+8, cols = 64 keys in 8 n-tiles) ----
        float s[8][4];
#pragma unroll
        for (int j = 0; j < 8; j++)
#pragma unroll
            for (int q = 0; q < 4; q++) s[j][q] = 0.f;

#pragma unroll
        for (int ks = 0; ks < 8; ks++) {
            uint32_t a[4];
            const uint32_t* ar = Qs + rowA * QP + ks * 8 + t;
            a[0] = ar[0]; a[1] = ar[8 * QP]; a[2] = ar[4]; a[3] = ar[8 * QP + 4];
#pragma unroll
            for (int j = 0; j < 8; j++) {
                uint32_t bb[2];
                const uint32_t* br = Ks + (j * 8 + g) * QP + ks * 8 + t;
                bb[0] = br[0]; bb[1] = br[4];
                mma_tf32(s[j], a, bb);
            }
        }

        // ---- scale + mask; online softmax ----
        float tm0 = -1e30f, tm1 = -1e30f;
#pragma unroll
        for (int j = 0; j < 8; j++) {
            const bool d0 = (msk[j * 8 + 2 * t] == 0);
            const bool d1 = (msk[j * 8 + 2 * t + 1] == 0);
            s[j][0] = d0 ? -1e12f : s[j][0] * 0.125f;
            s[j][1] = d1 ? -1e12f : s[j][1] * 0.125f;
            s[j][2] = d0 ? -1e12f : s[j][2] * 0.125f;
            s[j][3] = d1 ? -1e12f : s[j][3] * 0.125f;
            tm0 = fmaxf(tm0, fmaxf(s[j][0], s[j][1]));
            tm1 = fmaxf(tm1, fmaxf(s[j][2], s[j][3]));
        }
        tm0 = fmaxf(tm0, __shfl_xor_sync(0xffffffffu, tm0, 1));
        tm0 = fmaxf(tm0, __shfl_xor_sync(0xffffffffu, tm0, 2));
        tm1 = fmaxf(tm1, __shfl_xor_sync(0xffffffffu, tm1, 1));
        tm1 = fmaxf(tm1, __shfl_xor_sync(0xffffffffu, tm1, 2));

        const float mn0 = fmaxf(m0, tm0), mn1 = fmaxf(m1, tm1);
        const float al0 = __expf(m0 - mn0), al1 = __expf(m1 - mn1);
        m0 = mn0; m1 = mn1;

        float ts0 = 0.f, ts1 = 0.f;
#pragma unroll
        for (int j = 0; j < 8; j++) {
            s[j][0] = __expf(s[j][0] - mn0);
            s[j][1] = __expf(s[j][1] - mn0);
            s[j][2] = __expf(s[j][2] - mn1);
            s[j][3] = __expf(s[j][3] - mn1);
            ts0 += s[j][0] + s[j][1];
            ts1 += s[j][2] + s[j][3];
        }
        ts0 += __shfl_xor_sync(0xffffffffu, ts0, 1);
        ts0 += __shfl_xor_sync(0xffffffffu, ts0, 2);
        ts1 += __shfl_xor_sync(0xffffffffu, ts1, 1);
        ts1 += __shfl_xor_sync(0xffffffffu, ts1, 2);
        l0 = l0 * al0 + ts0;
        l1 = l1 * al1 + ts1;

#pragma unroll
        for (int j = 0; j < 8; j++) {
            o[j][0] *= al0; o[j][1] *= al0;
            o[j][2] *= al1; o[j][3] *= al1;
        }

        // ---- stage P (this warp's 16 rows) as tf32 bits ----
#pragma unroll
        for (int j = 0; j < 8; j++) {
            uint32_t* p0 = Ps + rowA * QP + j * 8 + 2 * t;
            uint32_t* p1 = Ps + (rowA + 8) * QP + j * 8 + 2 * t;
            p0[0] = f2tf32(s[j][0]); p0[1] = f2tf32(s[j][1]);
            p1[0] = f2tf32(s[j][2]); p1[1] = f2tf32(s[j][3]);
        }
        __syncwarp();   // P rows are private to this warp

        // ---- O += P V ----
#pragma unroll
        for (int ks = 0; ks < 8; ks++) {
            uint32_t a[4];
            const uint32_t* ar = Ps + rowA * QP + ks * 8 + t;
            a[0] = ar[0]; a[1] = ar[8 * QP]; a[2] = ar[4]; a[3] = ar[8 * QP + 4];
#pragma unroll
            for (int j = 0; j < 8; j++) {
                uint32_t bb[2];
                const uint32_t* br = Vs + (ks * 8 + t) * VP + j * 8 + g;
                bb[0] = br[0]; bb[1] = br[4 * VP];
                mma_tf32(o[j], a, bb);
            }
        }
    }

    // ---- epilogue: X = 0.5 * O / l ----
    const float sc0 = 0.5f / l0, sc1 = 0.5f / l1;
    float* Xr0 = X + ((size_t)b * 1024 + q0 + rowA) * 1024 + h * 64;
    float* Xr1 = Xr0 + (size_t)8 * 1024;
#pragma unroll
    for (int j = 0; j < 8; j++) {
        *(float2*)(Xr0 + j * 8 + 2 * t) = make_float2(o[j][0] * sc0, o[j][1] * sc0);
        *(float2*)(Xr1 + j * 8 + 2 * t) = make_float2(o[j][2] * sc1, o[j][3] * sc1);
    }
}

// ---------------------------------------------------------------------------
extern "C" void kernel_launch(void* const* d_in, const int* in_sizes, int n_in,
                              void* d_out, int out_size)
{
    const float* query = (const float*)d_in[0];
    const float* key   = (const float*)d_in[1];
    const float* value = (const float*)d_in[2];
    const float* adj   = (const float*)d_in[3];
    const int*   mask  = (const int*)d_in[5];
    const float* Wq = (const float*)d_in[6];
    const float* bq = (const float*)d_in[7];
    const float* Wk = (const float*)d_in[8];
    const float* bk = (const float*)d_in[9];
    const float* Wv = (const float*)d_in[10];
    const float* bv = (const float*)d_in[11];
    const float* Wo = (const float*)d_in[12];
    const float* bo = (const float*)d_in[13];
    float* out = (float*)d_out;

    float *pQ, *pK, *pV, *pX, *pInv;
    cudaGetSymbolAddress((void**)&pQ, g_Q);
    cudaGetSymbolAddress((void**)&pK, g_K);
    cudaGetSymbolAddress((void**)&pV, g_V);
    cudaGetSymbolAddress((void**)&pX, g_X);
    cudaGetSymbolAddress((void**)&pInv, g_inv);

    cudaFuncSetAttribute(gemm_tf32, cudaFuncAttributeMaxDynamicSharedMemorySize, GEMM_SMEM);
    cudaFuncSetAttribute(attn_tc, cudaFuncAttributeMaxDynamicSharedMemorySize, ATT_SMEM);

    dim3 gProj(4, 64, 1);

    gemm_tf32<<<gProj, 256, GEMM_SMEM>>>(query, Wq, bq, nullptr, nullptr, pQ, 0, 0, 0, 0);
    gemm_tf32<<<gProj, 256, GEMM_SMEM>>>(key,   Wk, bk, nullptr, nullptr, pK, 0, 0, 0, 0);
    gemm_tf32<<<gProj, 256, GEMM_SMEM>>>(value, Wv, bv, nullptr, nullptr, pV, 0, 0, 0, 0);

    rowsum_inv<<<8192, 256>>>(adj, pInv);

    // attention half -> X (tensor cores)
    dim3 gAtt(16, 16, 8);
    attn_tc<<<gAtt, 128, ATT_SMEM>>>(pQ, pK, pV, mask, pX);

    // adjacency half: X += 0.5 * diag(inv) * (adj @ V), batched
    gemm_tf32<<<dim3(4, 8, 8), 256, GEMM_SMEM>>>(
        adj, pV, nullptr, pInv, pX, pX,
        (size_t)1024 * 1024, (size_t)1024 * 1024, (size_t)1024 * 1024, 1);

    gemm_tf32<<<gProj, 256, GEMM_SMEM>>>(pX, Wo, bo, nullptr, nullptr, out, 0, 0, 0, 0);
}

// round 6
// speedup vs baseline: 3.3650x; 1.1978x over previous
#include <cuda_runtime.h>
#include <cstdint>

// ============================================================================
// Problem: B=8, N=1024, D=1024, H=16, dk=64
// out = (0.5*softmax(QK^T/8, key-masked) + 0.5*row_norm(adj)) @ V  -> @Wo + bo
// All heavy math on tensor cores via mma.sync tf32. All tf32 roundings hoisted
// out of GEMM mainloops: inputs pre-converted, intermediates stored tf32.
// ============================================================================

__device__ float g_Q[8u * 1024u * 1024u];     // tf32-valued
__device__ float g_K[8u * 1024u * 1024u];     // tf32-valued
__device__ float g_V[8u * 1024u * 1024u];     // tf32-valued
__device__ float g_X[8u * 1024u * 1024u];     // attn: fp32, after adj-gemm: tf32
__device__ float g_inv[8u * 1024u];
__device__ float g_tQin[8u * 1024u * 1024u];  // tf32(query)
__device__ float g_tKin[8u * 1024u * 1024u];  // tf32(key)
__device__ float g_tVin[8u * 1024u * 1024u];  // tf32(value)
__device__ float g_tAdj[8u * 1024u * 1024u];  // tf32(adj)
__device__ float g_tW[4u * 1024u * 1024u];    // tf32(Wq|Wk|Wv|Wo)

// ---------------------------------------------------------------------------
// PTX helpers
// ---------------------------------------------------------------------------
__device__ __forceinline__ uint32_t smem_to_u32(const void* p) {
    uint32_t a;
    asm("{ .reg .u64 t; cvta.to.shared.u64 t, %1; cvt.u32.u64 %0, t; }" : "=r"(a) : "l"(p));
    return a;
}
__device__ __forceinline__ void cp_async16(uint32_t s, const void* g) {
    asm volatile("cp.async.cg.shared.global [%0], [%1], 16;" :: "r"(s), "l"(g));
}
#define CP_COMMIT() asm volatile("cp.async.commit_group;" ::: "memory")
#define CP_WAIT(n)  asm volatile("cp.async.wait_group %0;" :: "n"(n) : "memory")

__device__ __forceinline__ uint32_t f2tf32(float x) {
    uint32_t r;
    asm("cvt.rna.tf32.f32 %0, %1;" : "=r"(r) : "f"(x));
    return r;
}
__device__ __forceinline__ float tf32f(float x) {   // tf32-rounded float
    return __uint_as_float(f2tf32(x));
}
__device__ __forceinline__ void mma_tf32(float* c, const uint32_t* a, const uint32_t* b) {
    asm volatile(
        "mma.sync.aligned.m16n8k8.row.col.f32.tf32.tf32.f32 "
        "{%0,%1,%2,%3}, {%4,%5,%6,%7}, {%8,%9}, {%0,%1,%2,%3};"
        : "+f"(c[0]), "+f"(c[1]), "+f"(c[2]), "+f"(c[3])
        : "r"(a[0]), "r"(a[1]), "r"(a[2]), "r"(a[3]), "r"(b[0]), "r"(b[1]));
}

// ---------------------------------------------------------------------------
// fp32 -> tf32-valued-fp32, elementwise (float4 per thread)
// ---------------------------------------------------------------------------
__global__ __launch_bounds__(256) void cvt_tf32(
    const float* __restrict__ in, float* __restrict__ out)
{
    int g = blockIdx.x * 256 + threadIdx.x;
    float4 v = ((const float4*)in)[g];
    float4 o = make_float4(tf32f(v.x), tf32f(v.y), tf32f(v.z), tf32f(v.w));
    ((float4*)out)[g] = o;
}

// ---------------------------------------------------------------------------
// tf32 tensor-core GEMM, cvt-free mainloop (inputs are tf32-valued floats).
// C[M, 1024] = A[M,1024] @ B[1024,1024]  (both row-major)
// Block tile 128x256, 8 warps (2x4), warp tile 64x64, K-tile 32, 3-stage cp.async.
// cmode 0: C = tf32(D + bias[col])
// cmode 1: C = tf32(0.5*inv[z*1024+row]*D + Xin[row,col])
// cmode 2: C = D + bias[col]   (full fp32 store, final output)
// ---------------------------------------------------------------------------
#define PA 36
#define PB 264
#define A_STG (128 * PA)             // 4608 floats
#define B_STG (32 * PB)              // 8448 floats
#define STG_STRIDE (A_STG + B_STG)   // 13056 floats
#define NSTG 3
#define GEMM_SMEM (STG_STRIDE * NSTG * 4)   // 156672 bytes

__global__ __launch_bounds__(256, 1) void gemm_tf32(
    const float* __restrict__ A, const float* __restrict__ B,
    const float* __restrict__ bias, const float* __restrict__ inv,
    const float* __restrict__ Xin, float* __restrict__ C,
    size_t sA, size_t sB, size_t sC, int cmode)
{
    extern __shared__ float sm[];
    uint32_t base_u = smem_to_u32(sm);

    const int tid = threadIdx.x;
    const int wid = tid >> 5, lane = tid & 31;
    const int wm = wid >> 2, wn = wid & 3;
    const int g = lane >> 2, t = lane & 3;

    const int z = blockIdx.z;
    const float* Ab = A + (size_t)z * sA + (size_t)(blockIdx.y * 128) * 1024;
    const float* Bb = B + (size_t)z * sB + blockIdx.x * 256;

    const int a_row = tid >> 3, a_c4 = (tid & 7) << 2;
    const int b_row = tid >> 6, b_c4 = (tid & 63) << 2;

    float c[4][8][4];
#pragma unroll
    for (int i = 0; i < 4; i++)
#pragma unroll
        for (int j = 0; j < 8; j++)
#pragma unroll
            for (int q = 0; q < 4; q++) c[i][j][q] = 0.f;

    auto load_stage = [&](int kt, int stg) {
        const uint32_t as_u = base_u + (uint32_t)(stg * STG_STRIDE) * 4;
        const uint32_t bs_u = as_u + (uint32_t)A_STG * 4;
#pragma unroll
        for (int i = 0; i < 4; i++) {
            int r = a_row + i * 32;
            cp_async16(as_u + (uint32_t)(r * PA + a_c4) * 4,
                       Ab + (size_t)r * 1024 + kt * 32 + a_c4);
        }
#pragma unroll
        for (int i = 0; i < 8; i++) {
            int r = b_row + i * 4;
            cp_async16(bs_u + (uint32_t)(r * PB + b_c4) * 4,
                       Bb + (size_t)(kt * 32 + r) * 1024 + b_c4);
        }
        CP_COMMIT();
    };

    load_stage(0, 0);
    load_stage(1, 1);

    int stg = 0;
    for (int kt = 0; kt < 32; kt++) {
        if (kt + 2 < 32) { load_stage(kt + 2, (kt + 2) % NSTG); CP_WAIT(2); }
        else if (kt + 1 < 32) { CP_WAIT(1); }
        else { CP_WAIT(0); }
        __syncthreads();

        const uint32_t* Ast = (const uint32_t*)(sm + stg * STG_STRIDE);
        const uint32_t* Bst = Ast + A_STG;
#pragma unroll
        for (int ks = 0; ks < 4; ks++) {
            const int k0 = ks * 8;
            uint32_t af[4][4];
#pragma unroll
            for (int i = 0; i < 4; i++) {
                const uint32_t* ar = Ast + (wm * 64 + i * 16 + g) * PA + k0 + t;
                af[i][0] = ar[0];
                af[i][1] = ar[8 * PA];
                af[i][2] = ar[4];
                af[i][3] = ar[8 * PA + 4];
            }
            uint32_t bf[8][2];
#pragma unroll
            for (int j = 0; j < 8; j++) {
                const uint32_t* br = Bst + (k0 + t) * PB + wn * 64 + j * 8 + g;
                bf[j][0] = br[0];
                bf[j][1] = br[4 * PB];
            }
#pragma unroll
            for (int i = 0; i < 4; i++)
#pragma unroll
                for (int j = 0; j < 8; j++)
                    mma_tf32(c[i][j], af[i], bf[j]);
        }
        __syncthreads();
        stg = (stg + 1) % NSTG;
    }

    // ---- epilogue ----
    const int colW = blockIdx.x * 256 + wn * 64;
    float* Cz = C + (size_t)z * sC;
    const float* Xz = Xin + (size_t)z * sC;

#pragma unroll
    for (int i = 0; i < 4; i++) {
        const int row0 = blockIdx.y * 128 + wm * 64 + i * 16 + g;
        const int row1 = row0 + 8;
        if (cmode == 0) {
#pragma unroll
            for (int j = 0; j < 8; j++) {
                const int col = colW + j * 8 + 2 * t;
                const float b0 = bias[col], b1 = bias[col + 1];
                *(float2*)(Cz + (size_t)row0 * 1024 + col) =
                    make_float2(tf32f(c[i][j][0] + b0), tf32f(c[i][j][1] + b1));
                *(float2*)(Cz + (size_t)row1 * 1024 + col) =
                    make_float2(tf32f(c[i][j][2] + b0), tf32f(c[i][j][3] + b1));
            }
        } else if (cmode == 1) {
            const float s0 = 0.5f * inv[z * 1024 + row0];
            const float s1 = 0.5f * inv[z * 1024 + row1];
#pragma unroll
            for (int j = 0; j < 8; j++) {
                const int col = colW + j * 8 + 2 * t;
                float2 x0 = *(const float2*)(Xz + (size_t)row0 * 1024 + col);
                float2 x1 = *(const float2*)(Xz + (size_t)row1 * 1024 + col);
                *(float2*)(Cz + (size_t)row0 * 1024 + col) =
                    make_float2(tf32f(s0 * c[i][j][0] + x0.x), tf32f(s0 * c[i][j][1] + x0.y));
                *(float2*)(Cz + (size_t)row1 * 1024 + col) =
                    make_float2(tf32f(s1 * c[i][j][2] + x1.x), tf32f(s1 * c[i][j][3] + x1.y));
            }
        } else {
#pragma unroll
            for (int j = 0; j < 8; j++) {
                const int col = colW + j * 8 + 2 * t;
                const float b0 = bias[col], b1 = bias[col + 1];
                *(float2*)(Cz + (size_t)row0 * 1024 + col) =
                    make_float2(c[i][j][0] + b0, c[i][j][1] + b1);
                *(float2*)(Cz + (size_t)row1 * 1024 + col) =
                    make_float2(c[i][j][2] + b0, c[i][j][3] + b1);
            }
        }
    }
}

// ---------------------------------------------------------------------------
// adjacency row-sum -> 1/(sum+eps)
// ---------------------------------------------------------------------------
__global__ __launch_bounds__(256) void rowsum_inv(
    const float* __restrict__ adj, float* __restrict__ inv)
{
    __shared__ float red[256];
    const int row = blockIdx.x;
    const float* a = adj + (size_t)row * 1024;
    float s = 0.f;
    for (int i = threadIdx.x; i < 1024; i += 256) s += a[i];
    red[threadIdx.x] = s;
    __syncthreads();
    for (int o = 128; o > 0; o >>= 1) {
        if (threadIdx.x < o) red[threadIdx.x] += red[threadIdx.x + o];
        __syncthreads();
    }
    if (threadIdx.x == 0) inv[row] = 1.0f / (red[0] + 1e-6f);
}

// ---------------------------------------------------------------------------
// Tensor-core flash attention half (Q/K/V already tf32-valued -> no cvt on load)
// X[b, q, h*64+d] = 0.5 * softmax(QK^T/8, key-masked) @ V
// ---------------------------------------------------------------------------
#define QP 68
#define VP 72
#define ATT_SMEM ((64 * (3 * QP + VP)) * 4)   // 70656 bytes

__global__ __launch_bounds__(128) void attn_tc(
    const float* __restrict__ Q, const float* __restrict__ K,
    const float* __restrict__ V, const int* __restrict__ mask,
    float* __restrict__ X)
{
    extern __shared__ uint32_t smu[];
    uint32_t* Qs = smu;
    uint32_t* Ks = smu + 64 * QP;
    uint32_t* Ps = smu + 128 * QP;
    uint32_t* Vs = smu + 192 * QP;
    __shared__ int msk[64];

    const int tid = threadIdx.x;
    const int wid = tid >> 5, lane = tid & 31;
    const int g = lane >> 2, t = lane & 3;
    const int b = blockIdx.z, h = blockIdx.y;
    const int q0 = blockIdx.x * 64;

    const float* Qb = Q + ((size_t)b * 1024 + q0) * 1024 + h * 64;
    const float* Kb = K + (size_t)b * 1024 * 1024 + h * 64;
    const float* Vb = V + (size_t)b * 1024 * 1024 + h * 64;
    const int* mb = mask + b * 1024;

    for (int idx = tid; idx < 64 * 16; idx += 128) {
        int r = idx >> 4, c4 = (idx & 15) << 2;
        float4 v = *(const float4*)(Qb + (size_t)r * 1024 + c4);
        uint32_t* d = Qs + r * QP + c4;
        d[0] = __float_as_uint(v.x); d[1] = __float_as_uint(v.y);
        d[2] = __float_as_uint(v.z); d[3] = __float_as_uint(v.w);
    }

    float m0 = -1e30f, m1 = -1e30f, l0 = 0.f, l1 = 0.f;
    float o[8][4];
#pragma unroll
    for (int j = 0; j < 8; j++)
#pragma unroll
        for (int q = 0; q < 4; q++) o[j][q] = 0.f;

    const int rowA = wid * 16 + g;

    for (int kb = 0; kb < 1024; kb += 64) {
        __syncthreads();
        for (int idx = tid; idx < 64 * 16; idx += 128) {
            int r = idx >> 4, c4 = (idx & 15) << 2;
            float4 kv = *(const float4*)(Kb + (size_t)(kb + r) * 1024 + c4);
            uint32_t* dk = Ks + r * QP + c4;
            dk[0] = __float_as_uint(kv.x); dk[1] = __float_as_uint(kv.y);
            dk[2] = __float_as_uint(kv.z); dk[3] = __float_as_uint(kv.w);
            float4 vv = *(const float4*)(Vb + (size_t)(kb + r) * 1024 + c4);
            uint32_t* dv = Vs + r * VP + c4;
            dv[0] = __float_as_uint(vv.x); dv[1] = __float_as_uint(vv.y);
            dv[2] = __float_as_uint(vv.z); dv[3] = __float_as_uint(vv.w);
        }
        if (tid < 64) msk[tid] = mb[kb + tid];
        __syncthreads();

        float s[8][4];
#pragma unroll
        for (int j = 0; j < 8; j++)
#pragma unroll
            for (int q = 0; q < 4; q++) s[j][q] = 0.f;

#pragma unroll
        for (int ks = 0; ks < 8; ks++) {
            uint32_t a[4];
            const uint32_t* ar = Qs + rowA * QP + ks * 8 + t;
            a[0] = ar[0]; a[1] = ar[8 * QP]; a[2] = ar[4]; a[3] = ar[8 * QP + 4];
#pragma unroll
            for (int j = 0; j < 8; j++) {
                uint32_t bb[2];
                const uint32_t* br = Ks + (j * 8 + g) * QP + ks * 8 + t;
                bb[0] = br[0]; bb[1] = br[4];
                mma_tf32(s[j], a, bb);
            }
        }

        float tm0 = -1e30f, tm1 = -1e30f;
#pragma unroll
        for (int j = 0; j < 8; j++) {
            const bool d0 = (msk[j * 8 + 2 * t] == 0);
            const bool d1 = (msk[j * 8 + 2 * t + 1] == 0);
            s[j][0] = d0 ? -1e12f : s[j][0] * 0.125f;
            s[j][1] = d1 ? -1e12f : s[j][1] * 0.125f;
            s[j][2] = d0 ? -1e12f : s[j][2] * 0.125f;
            s[j][3] = d1 ? -1e12f : s[j][3] * 0.125f;
            tm0 = fmaxf(tm0, fmaxf(s[j][0], s[j][1]));
            tm1 = fmaxf(tm1, fmaxf(s[j][2], s[j][3]));
        }
        tm0 = fmaxf(tm0, __shfl_xor_sync(0xffffffffu, tm0, 1));
        tm0 = fmaxf(tm0, __shfl_xor_sync(0xffffffffu, tm0, 2));
        tm1 = fmaxf(tm1, __shfl_xor_sync(0xffffffffu, tm1, 1));
        tm1 = fmaxf(tm1, __shfl_xor_sync(0xffffffffu, tm1, 2));

        const float mn0 = fmaxf(m0, tm0), mn1 = fmaxf(m1, tm1);
        const float al0 = __expf(m0 - mn0), al1 = __expf(m1 - mn1);
        m0 = mn0; m1 = mn1;

        float ts0 = 0.f, ts1 = 0.f;
#pragma unroll
        for (int j = 0; j < 8; j++) {
            s[j][0] = __expf(s[j][0] - mn0);
            s[j][1] = __expf(s[j][1] - mn0);
            s[j][2] = __expf(s[j][2] - mn1);
            s[j][3] = __expf(s[j][3] - mn1);
            ts0 += s[j][0] + s[j][1];
            ts1 += s[j][2] + s[j][3];
        }
        ts0 += __shfl_xor_sync(0xffffffffu, ts0, 1);
        ts0 += __shfl_xor_sync(0xffffffffu, ts0, 2);
        ts1 += __shfl_xor_sync(0xffffffffu, ts1, 1);
        ts1 += __shfl_xor_sync(0xffffffffu, ts1, 2);
        l0 = l0 * al0 + ts0;
        l1 = l1 * al1 + ts1;

#pragma unroll
        for (int j = 0; j < 8; j++) {
            o[j][0] *= al0; o[j][1] *= al0;
            o[j][2] *= al1; o[j][3] *= al1;
        }

#pragma unroll
        for (int j = 0; j < 8; j++) {
            uint32_t* p0 = Ps + rowA * QP + j * 8 + 2 * t;
            uint32_t* p1 = Ps + (rowA + 8) * QP + j * 8 + 2 * t;
            p0[0] = f2tf32(s[j][0]); p0[1] = f2tf32(s[j][1]);
            p1[0] = f2tf32(s[j][2]); p1[1] = f2tf32(s[j][3]);
        }
        __syncwarp();

#pragma unroll
        for (int ks = 0; ks < 8; ks++) {
            uint32_t a[4];
            const uint32_t* ar = Ps + rowA * QP + ks * 8 + t;
            a[0] = ar[0]; a[1] = ar[8 * QP]; a[2] = ar[4]; a[3] = ar[8 * QP + 4];
#pragma unroll
            for (int j = 0; j < 8; j++) {
                uint32_t bb[2];
                const uint32_t* br = Vs + (ks * 8 + t) * VP + j * 8 + g;
                bb[0] = br[0]; bb[1] = br[4 * VP];
                mma_tf32(o[j], a, bb);
            }
        }
    }

    const float sc0 = 0.5f / l0, sc1 = 0.5f / l1;
    float* Xr0 = X + ((size_t)b * 1024 + q0 + rowA) * 1024 + h * 64;
    float* Xr1 = Xr0 + (size_t)8 * 1024;
#pragma unroll
    for (int j = 0; j < 8; j++) {
        *(float2*)(Xr0 + j * 8 + 2 * t) = make_float2(o[j][0] * sc0, o[j][1] * sc0);
        *(float2*)(Xr1 + j * 8 + 2 * t) = make_float2(o[j][2] * sc1, o[j][3] * sc1);
    }
}

// ---------------------------------------------------------------------------
extern "C" void kernel_launch(void* const* d_in, const int* in_sizes, int n_in,
                              void* d_out, int out_size)
{
    const float* query = (const float*)d_in[0];
    const float* key   = (const float*)d_in[1];
    const float* value = (const float*)d_in[2];
    const float* adj   = (const float*)d_in[3];
    const int*   mask  = (const int*)d_in[5];
    const float* Wq = (const float*)d_in[6];
    const float* bq = (const float*)d_in[7];
    const float* Wk = (const float*)d_in[8];
    const float* bk = (const float*)d_in[9];
    const float* Wv = (const float*)d_in[10];
    const float* bv = (const float*)d_in[11];
    const float* Wo = (const float*)d_in[12];
    const float* bo = (const float*)d_in[13];
    float* out = (float*)d_out;

    float *pQ, *pK, *pV, *pX, *pInv, *ptQ, *ptK, *ptV, *ptAdj, *ptW;
    cudaGetSymbolAddress((void**)&pQ, g_Q);
    cudaGetSymbolAddress((void**)&pK, g_K);
    cudaGetSymbolAddress((void**)&pV, g_V);
    cudaGetSymbolAddress((void**)&pX, g_X);
    cudaGetSymbolAddress((void**)&pInv, g_inv);
    cudaGetSymbolAddress((void**)&ptQ, g_tQin);
    cudaGetSymbolAddress((void**)&ptK, g_tKin);
    cudaGetSymbolAddress((void**)&ptV, g_tVin);
    cudaGetSymbolAddress((void**)&ptAdj, g_tAdj);
    cudaGetSymbolAddress((void**)&ptW, g_tW);

    float* ptWq = ptW;
    float* ptWk = ptW + 1024u * 1024u;
    float* ptWv = ptW + 2u * 1024u * 1024u;
    float* ptWo = ptW + 3u * 1024u * 1024u;

    cudaFuncSetAttribute(gemm_tf32, cudaFuncAttributeMaxDynamicSharedMemorySize, GEMM_SMEM);
    cudaFuncSetAttribute(attn_tc, cudaFuncAttributeMaxDynamicSharedMemorySize, ATT_SMEM);

    // pre-convert all GEMM inputs to tf32-valued fp32
    cvt_tf32<<<8192, 256>>>(query, ptQ);
    cvt_tf32<<<8192, 256>>>(key,   ptK);
    cvt_tf32<<<8192, 256>>>(value, ptV);
    cvt_tf32<<<8192, 256>>>(adj,   ptAdj);
    cvt_tf32<<<1024, 256>>>(Wq, ptWq);
    cvt_tf32<<<1024, 256>>>(Wk, ptWk);
    cvt_tf32<<<1024, 256>>>(Wv, ptWv);
    cvt_tf32<<<1024, 256>>>(Wo, ptWo);

    dim3 gProj(4, 64, 1);

    // projections -> tf32-valued Q/K/V
    gemm_tf32<<<gProj, 256, GEMM_SMEM>>>(ptQ, ptWq, bq, nullptr, nullptr, pQ, 0, 0, 0, 0);
    gemm_tf32<<<gProj, 256, GEMM_SMEM>>>(ptK, ptWk, bk, nullptr, nullptr, pK, 0, 0, 0, 0);
    gemm_tf32<<<gProj, 256, GEMM_SMEM>>>(ptV, ptWv, bv, nullptr, nullptr, pV, 0, 0, 0, 0);

    rowsum_inv<<<8192, 256>>>(adj, pInv);

    // attention half -> X (fp32)
    dim3 gAtt(16, 16, 8);
    attn_tc<<<gAtt, 128, ATT_SMEM>>>(pQ, pK, pV, mask, pX);

    // adjacency half: X = tf32(0.5*diag(inv)*(adj@V) + X), batched
    gemm_tf32<<<dim3(4, 8, 8), 256, GEMM_SMEM>>>(
        ptAdj, pV, nullptr, pInv, pX, pX,
        (size_t)1024 * 1024, (size_t)1024 * 1024, (size_t)1024 * 1024, 1);

    // output projection (full fp32 store)
    gemm_tf32<<<gProj, 256, GEMM_SMEM>>>(pX, ptWo, bo, nullptr, nullptr, out, 0, 0, 0, 2);
}